// round 3
// baseline (speedup 1.0000x reference)
#include <cuda_runtime.h>

#define MAX_NODES 100000
#define MAX_EDGES 1600000
#define N_GRAPHS  1024
#define N_FEAT    128
#define HID       64
#define N_CLASSES 16
#define N_CENT    3

// ---------------- scratch (no allocation allowed) ----------------
__device__ float g_deg [MAX_NODES];
__device__ float g_dinv[MAX_NODES];
__device__ float g_hw  [(size_t)MAX_NODES * HID];
__device__ float g_agg [(size_t)MAX_NODES * HID];
__device__ float g_sums[N_GRAPHS * HID];
__device__ float g_cnt [N_GRAPHS];

// ---------------- degree / norm ----------------
__global__ void k_init_deg(int n) {
    int i = blockIdx.x * blockDim.x + threadIdx.x;
    if (i < n) g_deg[i] = 1.0f;   // self-loop contributes 1
}

__global__ void k_deg_accum(const int* __restrict__ dst, int E) {
    int e = blockIdx.x * blockDim.x + threadIdx.x;
    if (e < E) atomicAdd(&g_deg[dst[e]], 1.0f);
}

__global__ void k_dinv(int n) {
    int i = blockIdx.x * blockDim.x + threadIdx.x;
    if (i < n) g_dinv[i] = rsqrtf(g_deg[i]);   // deg >= 1 always
}

// ---------------- GEMM: g_hw[n,64] = act(in[n,K]) @ W[K,64] ----------------
// FROM_AGG: read input from g_agg symbol (layers 2/3); else from `in` pointer.
// ACT: input activation = relu(v + bias[k])  (folds previous layer's bias+relu)
template <int K, bool FROM_AGG, bool ACT>
__global__ void k_gemm(const float* __restrict__ in, const float* __restrict__ W,
                       const float* __restrict__ bias, int n) {
    __shared__ float Ws[K * HID];
    __shared__ float Xs[16 * K];
    const int tid  = threadIdx.x;           // 256 threads
    const int base = blockIdx.x * 16;

    for (int i = tid; i < K * HID; i += 256) Ws[i] = W[i];
    for (int i = tid; i < 16 * K; i += 256) {
        int r = i / K, k = i - r * K;
        int node = base + r;
        float v = 0.0f;
        if (node < n) {
            v = FROM_AGG ? g_agg[(size_t)node * K + k] : in[(size_t)node * K + k];
            if (ACT) v = fmaxf(v + bias[k], 0.0f);
        }
        Xs[i] = v;
    }
    __syncthreads();

    const int col = tid & 63;
    const int ng  = tid >> 6;   // 0..3, handles nodes ng, ng+4, ng+8, ng+12
    float a0 = 0.f, a1 = 0.f, a2 = 0.f, a3 = 0.f;
#pragma unroll 4
    for (int k = 0; k < K; k++) {
        float w = Ws[k * HID + col];
        a0 = fmaf(Xs[(ng +  0) * K + k], w, a0);
        a1 = fmaf(Xs[(ng +  4) * K + k], w, a1);
        a2 = fmaf(Xs[(ng +  8) * K + k], w, a2);
        a3 = fmaf(Xs[(ng + 12) * K + k], w, a3);
    }
    int n0 = base + ng;
    if (n0      < n) g_hw[(size_t)(n0     ) * HID + col] = a0;
    if (n0 + 4  < n) g_hw[(size_t)(n0 +  4) * HID + col] = a1;
    if (n0 + 8  < n) g_hw[(size_t)(n0 +  8) * HID + col] = a2;
    if (n0 + 12 < n) g_hw[(size_t)(n0 + 12) * HID + col] = a3;
}

// ---------------- self-loop init: agg[i,:] = dinv[i]^2 * hw[i,:] ----------------
__global__ void k_selfloop(int n) {
    int idx = blockIdx.x * blockDim.x + threadIdx.x;
    if (idx < n * HID) {
        int i = idx >> 6;
        float di = g_dinv[i];
        g_agg[idx] = di * di * g_hw[idx];
    }
}

// ---------------- edge scatter: agg[dst,:] += dinv[s]*dinv[d]*hw[src,:] ----------------
__global__ void k_scatter(const int* __restrict__ src,
                          const int* __restrict__ dst, int E) {
    int warp = (blockIdx.x * blockDim.x + threadIdx.x) >> 5;
    int lane = threadIdx.x & 31;
    if (warp >= E) return;
    int s = src[warp];
    int d = dst[warp];
    float nrm = g_dinv[s] * g_dinv[d];
    const float* hs = g_hw + (size_t)s * HID;
    float*       ad = g_agg + (size_t)d * HID;
    atomicAdd(ad + lane,      nrm * hs[lane]);
    atomicAdd(ad + lane + 32, nrm * hs[lane + 32]);
}

// ---------------- pooling ----------------
__global__ void k_zero_pool() {
    int idx = blockIdx.x * blockDim.x + threadIdx.x;
    if (idx < N_GRAPHS * HID) g_sums[idx] = 0.0f;
    if (idx < N_GRAPHS)       g_cnt[idx]  = 0.0f;
}

__global__ void k_pool(const int* __restrict__ batch, int n) {
    int warp = (blockIdx.x * blockDim.x + threadIdx.x) >> 5;
    int lane = threadIdx.x & 31;
    if (warp >= n) return;
    int b = batch[warp];
    atomicAdd(&g_sums[b * HID + lane],      g_agg[(size_t)warp * HID + lane]);
    atomicAdd(&g_sums[b * HID + lane + 32], g_agg[(size_t)warp * HID + lane + 32]);
    if (lane == 0) atomicAdd(&g_cnt[b], 1.0f);
}

// ---------------- head: centroid distances ----------------
__global__ void k_head(const float* __restrict__ b3, const float* __restrict__ C,
                       const float* __restrict__ rbias, float* __restrict__ out) {
    int g = blockIdx.x;
    int tid = threadIdx.x;   // 64 threads
    __shared__ float emb[HID];
    __shared__ float d48[N_CLASSES * N_CENT];
    __shared__ float dpc[N_CLASSES];

    float cnt = fmaxf(g_cnt[g], 1.0f);
    emb[tid] = g_sums[g * HID + tid] / cnt + b3[tid];
    __syncthreads();

    if (tid < N_CLASSES * N_CENT) {
        const float* c = C + tid * HID;
        float acc = 0.0f;
#pragma unroll
        for (int k = 0; k < HID; k++) {
            float df = emb[k] - c[k];
            acc = fmaf(df, df, acc);
        }
        d48[tid] = acc;
    }
    __syncthreads();
    if (tid < N_CLASSES) {
        float m = fminf(d48[tid * 3], fminf(d48[tid * 3 + 1], d48[tid * 3 + 2]));
        dpc[tid] = m;
        out[g * 17 + tid] = -m;
    }
    __syncthreads();
    if (tid == 0) {
        float m = dpc[0];
#pragma unroll
        for (int i = 1; i < N_CLASSES; i++) m = fminf(m, dpc[i]);
        out[g * 17 + 16] = m - rbias[0];
    }
}

// ---------------- launch ----------------
extern "C" void kernel_launch(void* const* d_in, const int* in_sizes, int n_in,
                              void* d_out, int out_size) {
    const float* x     = (const float*)d_in[0];
    const int*   ei    = (const int*)d_in[1];     // JAX default: int32 (x64 disabled)
    const int*   batch = (const int*)d_in[2];
    const float* W1    = (const float*)d_in[3];
    const float* b1    = (const float*)d_in[4];
    const float* W2    = (const float*)d_in[5];
    const float* b2    = (const float*)d_in[6];
    const float* W3    = (const float*)d_in[7];
    const float* b3    = (const float*)d_in[8];
    const float* C     = (const float*)d_in[9];
    const float* rb    = (const float*)d_in[10];
    float* out = (float*)d_out;

    int n = in_sizes[0] / N_FEAT;
    int E = in_sizes[1] / 2;
    const int* src = ei;
    const int* dst = ei + E;

    // degree + norm
    k_init_deg<<<(n + 255) / 256, 256>>>(n);
    k_deg_accum<<<(E + 255) / 256, 256>>>(dst, E);
    k_dinv<<<(n + 255) / 256, 256>>>(n);

    int gemmBlocks    = (n + 15) / 16;
    int slBlocks      = (n * HID + 255) / 256;
    int scatterBlocks = (int)(((long long)E * 32 + 255) / 256);   // E warps, 8 warps/block

    // ---- layer 1 ----
    k_gemm<N_FEAT, false, false><<<gemmBlocks, 256>>>(x, W1, nullptr, n);
    k_selfloop<<<slBlocks, 256>>>(n);
    k_scatter<<<scatterBlocks, 256>>>(src, dst, E);

    // ---- layer 2 (bias1+relu folded into GEMM input) ----
    k_gemm<HID, true, true><<<gemmBlocks, 256>>>(nullptr, W2, b1, n);
    k_selfloop<<<slBlocks, 256>>>(n);
    k_scatter<<<scatterBlocks, 256>>>(src, dst, E);

    // ---- layer 3 (bias2+relu folded) ----
    k_gemm<HID, true, true><<<gemmBlocks, 256>>>(nullptr, W3, b2, n);
    k_selfloop<<<slBlocks, 256>>>(n);
    k_scatter<<<scatterBlocks, 256>>>(src, dst, E);

    // ---- pool (bias3 folded into head) ----
    k_zero_pool<<<(N_GRAPHS * HID + 255) / 256, 256>>>();
    k_pool<<<(int)(((long long)n * 32 + 255) / 256), 256>>>(batch, n);

    // ---- head ----
    k_head<<<N_GRAPHS, HID>>>(b3, C, rb, out);
}

// round 5
// speedup vs baseline: 1.5040x; 1.5040x over previous
#include <cuda_runtime.h>

#define MAX_NODES 100000
#define MAX_EDGES 1600000
#define N_GRAPHS  1024
#define N_FEAT    128
#define HID       64
#define N_CLASSES 16
#define N_CENT    3

// ---------------- scratch (no allocation allowed) ----------------
__device__ int   g_indeg   [MAX_NODES];
__device__ int   g_rowstart[MAX_NODES];
__device__ int   g_cursor  [MAX_NODES];
__device__ int   g_csr_src [MAX_EDGES];
__device__ float g_dinv[MAX_NODES];
__device__ float g_hw  [(size_t)MAX_NODES * HID];
__device__ float g_agg [(size_t)MAX_NODES * HID];
__device__ float g_sums[N_GRAPHS * HID];
__device__ float g_cnt [N_GRAPHS];

// ---------------- degree / CSR build ----------------
__global__ void k_zero_indeg(int n) {
    int i = blockIdx.x * blockDim.x + threadIdx.x;
    if (i < n) g_indeg[i] = 0;
}

__global__ void k_count(const int* __restrict__ dst, int E) {
    int e = blockIdx.x * blockDim.x + threadIdx.x;
    if (e < E) atomicAdd(&g_indeg[dst[e]], 1);
}

__global__ void k_dinv(int n) {
    int i = blockIdx.x * blockDim.x + threadIdx.x;
    if (i < n) g_dinv[i] = rsqrtf((float)(g_indeg[i] + 1));  // +1 self-loop
}

// single-block exclusive scan of indeg -> rowstart, cursor
__global__ void k_scan(int n) {
    __shared__ int part[1024];
    int t = threadIdx.x;
    int chunk = (n + 1023) >> 10;
    int b = t * chunk, e = min(n, b + chunk);
    int s = 0;
    for (int i = b; i < e; i++) s += g_indeg[i];
    part[t] = s;
    __syncthreads();
    // Hillis-Steele inclusive scan
    for (int off = 1; off < 1024; off <<= 1) {
        int v = (t >= off) ? part[t - off] : 0;
        __syncthreads();
        part[t] += v;
        __syncthreads();
    }
    int base = (t == 0) ? 0 : part[t - 1];
    for (int i = b; i < e; i++) {
        g_rowstart[i] = base;
        g_cursor[i]   = base;
        base += g_indeg[i];
    }
}

__global__ void k_fill(const int* __restrict__ src, const int* __restrict__ dst, int E) {
    int e = blockIdx.x * blockDim.x + threadIdx.x;
    if (e < E) {
        int pos = atomicAdd(&g_cursor[dst[e]], 1);
        g_csr_src[pos] = src[e];
    }
}

// ---------------- GEMM: g_hw[n,64] = act(in[n,K]) @ W[K,64] ----------------
// Register-tiled: 64 nodes x 64 cols per block, 256 threads, 16 out/thread.
// FROM_AGG: read from g_agg (layers 2/3). ACT: relu(v + bias[k]) on input.
template <int K, bool FROM_AGG, bool ACT>
__global__ void __launch_bounds__(256) k_gemm(const float* __restrict__ in,
                                              const float* __restrict__ W,
                                              const float* __restrict__ bias, int n) {
    constexpr int XS_STRIDE = K + 4;           // pad to avoid bank conflicts
    __shared__ float Ws[K * HID];
    __shared__ float Xs[64 * XS_STRIDE];
    __shared__ float Bs[K];

    const int tid  = threadIdx.x;
    const int base = blockIdx.x * 64;

    for (int i = tid; i < K * HID; i += 256) Ws[i] = W[i];
    if (ACT) for (int i = tid; i < K; i += 256) Bs[i] = bias[i];

    // fill Xs: 64 rows of K floats, vectorized
    const float* xin = FROM_AGG ? (const float*)g_agg : in;
    for (int i = tid; i < 64 * (K / 4); i += 256) {
        int r = i / (K / 4), kq = i - r * (K / 4);
        int node = base + r;
        float4 v = make_float4(0.f, 0.f, 0.f, 0.f);
        if (node < n) v = ((const float4*)(xin + (size_t)node * K))[kq];
        float* xr = Xs + r * XS_STRIDE + kq * 4;
        xr[0] = v.x; xr[1] = v.y; xr[2] = v.z; xr[3] = v.w;
    }
    __syncthreads();

    const int cg = tid & 15;        // col group: cols cg*4..cg*4+3
    const int ng = tid >> 4;        // node: ng, ng+16, ng+32, ng+48
    float acc[4][4];
#pragma unroll
    for (int i = 0; i < 4; i++)
#pragma unroll
        for (int j = 0; j < 4; j++) acc[i][j] = 0.0f;

#pragma unroll 4
    for (int k = 0; k < K; k++) {
        float4 w = *(const float4*)(Ws + k * HID + cg * 4);
        float xv[4];
#pragma unroll
        for (int i = 0; i < 4; i++) {
            float v = Xs[(ng + 16 * i) * XS_STRIDE + k];
            if (ACT) v = fmaxf(v + Bs[k], 0.0f);
            xv[i] = v;
        }
#pragma unroll
        for (int i = 0; i < 4; i++) {
            acc[i][0] = fmaf(xv[i], w.x, acc[i][0]);
            acc[i][1] = fmaf(xv[i], w.y, acc[i][1]);
            acc[i][2] = fmaf(xv[i], w.z, acc[i][2]);
            acc[i][3] = fmaf(xv[i], w.w, acc[i][3]);
        }
    }

#pragma unroll
    for (int i = 0; i < 4; i++) {
        int node = base + ng + 16 * i;
        if (node < n) {
            float4 v = make_float4(acc[i][0], acc[i][1], acc[i][2], acc[i][3]);
            *((float4*)(g_hw + (size_t)node * HID + cg * 4)) = v;
        }
    }
}

// ---------------- gather: agg[d,:] = dinv[d]^2*hw[d,:] + sum_e dinv[s]dinv[d]*hw[s,:] ----------------
__global__ void k_gather(int n) {
    int w    = (blockIdx.x * blockDim.x + threadIdx.x) >> 5;
    int lane = threadIdx.x & 31;
    if (w >= n) return;
    float dd = g_dinv[w];
    const float* hw0 = g_hw + (size_t)w * HID;
    float a0 = dd * dd * hw0[lane];
    float a1 = dd * dd * hw0[lane + 32];
    int beg = g_rowstart[w];
    int end = beg + g_indeg[w];
    int j = beg;
    // software-pipelined: prefetch next src index
    if (j < end) {
        int s = g_csr_src[j];
        for (; j + 1 < end; j++) {
            int s_next = g_csr_src[j + 1];
            float nrm = dd * g_dinv[s];
            const float* hs = g_hw + (size_t)s * HID;
            a0 = fmaf(nrm, hs[lane],      a0);
            a1 = fmaf(nrm, hs[lane + 32], a1);
            s = s_next;
        }
        float nrm = dd * g_dinv[s];
        const float* hs = g_hw + (size_t)s * HID;
        a0 = fmaf(nrm, hs[lane],      a0);
        a1 = fmaf(nrm, hs[lane + 32], a1);
    }
    g_agg[(size_t)w * HID + lane]      = a0;
    g_agg[(size_t)w * HID + lane + 32] = a1;
}

// ---------------- pooling ----------------
__global__ void k_zero_pool() {
    int idx = blockIdx.x * blockDim.x + threadIdx.x;
    if (idx < N_GRAPHS * HID) g_sums[idx] = 0.0f;
    if (idx < N_GRAPHS)       g_cnt[idx]  = 0.0f;
}

__global__ void k_pool(const int* __restrict__ batch, int n) {
    int w    = (blockIdx.x * blockDim.x + threadIdx.x) >> 5;
    int lane = threadIdx.x & 31;
    if (w >= n) return;
    int b = batch[w];
    atomicAdd(&g_sums[b * HID + lane],      g_agg[(size_t)w * HID + lane]);
    atomicAdd(&g_sums[b * HID + lane + 32], g_agg[(size_t)w * HID + lane + 32]);
    if (lane == 0) atomicAdd(&g_cnt[b], 1.0f);
}

// ---------------- head: centroid distances ----------------
__global__ void k_head(const float* __restrict__ b3, const float* __restrict__ C,
                       const float* __restrict__ rbias, float* __restrict__ out) {
    int g = blockIdx.x;
    int tid = threadIdx.x;   // 64 threads
    __shared__ float emb[HID];
    __shared__ float d48[N_CLASSES * N_CENT];
    __shared__ float dpc[N_CLASSES];

    float cnt = fmaxf(g_cnt[g], 1.0f);
    emb[tid] = g_sums[g * HID + tid] / cnt + b3[tid];
    __syncthreads();

    if (tid < N_CLASSES * N_CENT) {
        const float* c = C + tid * HID;
        float acc = 0.0f;
#pragma unroll
        for (int k = 0; k < HID; k++) {
            float df = emb[k] - c[k];
            acc = fmaf(df, df, acc);
        }
        d48[tid] = acc;
    }
    __syncthreads();
    if (tid < N_CLASSES) {
        float m = fminf(d48[tid * 3], fminf(d48[tid * 3 + 1], d48[tid * 3 + 2]));
        dpc[tid] = m;
        out[g * 17 + tid] = -m;
    }
    __syncthreads();
    if (tid == 0) {
        float m = dpc[0];
#pragma unroll
        for (int i = 1; i < N_CLASSES; i++) m = fminf(m, dpc[i]);
        out[g * 17 + 16] = m - rbias[0];
    }
}

// ---------------- launch ----------------
extern "C" void kernel_launch(void* const* d_in, const int* in_sizes, int n_in,
                              void* d_out, int out_size) {
    const float* x     = (const float*)d_in[0];
    const int*   ei    = (const int*)d_in[1];     // JAX default int32 (x64 disabled)
    const int*   batch = (const int*)d_in[2];
    const float* W1    = (const float*)d_in[3];
    const float* b1    = (const float*)d_in[4];
    const float* W2    = (const float*)d_in[5];
    const float* b2    = (const float*)d_in[6];
    const float* W3    = (const float*)d_in[7];
    const float* b3    = (const float*)d_in[8];
    const float* C     = (const float*)d_in[9];
    const float* rb    = (const float*)d_in[10];
    float* out = (float*)d_out;

    int n = in_sizes[0] / N_FEAT;
    int E = in_sizes[1] / 2;
    const int* src = ei;
    const int* dst = ei + E;

    // ---- CSR build (once per launch) ----
    k_zero_indeg<<<(n + 255) / 256, 256>>>(n);
    k_count<<<(E + 255) / 256, 256>>>(dst, E);
    k_dinv<<<(n + 255) / 256, 256>>>(n);
    k_scan<<<1, 1024>>>(n);
    k_fill<<<(E + 255) / 256, 256>>>(src, dst, E);

    int gemmBlocks   = (n + 63) / 64;
    int gatherBlocks = (int)(((long long)n * 32 + 255) / 256);   // warp per node

    // ---- layer 1 ----
    k_gemm<N_FEAT, false, false><<<gemmBlocks, 256>>>(x, W1, nullptr, n);
    k_gather<<<gatherBlocks, 256>>>(n);

    // ---- layer 2 (bias1+relu folded into GEMM input) ----
    k_gemm<HID, true, true><<<gemmBlocks, 256>>>(nullptr, W2, b1, n);
    k_gather<<<gatherBlocks, 256>>>(n);

    // ---- layer 3 (bias2+relu folded) ----
    k_gemm<HID, true, true><<<gemmBlocks, 256>>>(nullptr, W3, b2, n);
    k_gather<<<gatherBlocks, 256>>>(n);

    // ---- pool (bias3 folded into head) ----
    k_zero_pool<<<(N_GRAPHS * HID + 255) / 256, 256>>>();
    k_pool<<<gatherBlocks, 256>>>(batch, n);

    // ---- head ----
    k_head<<<N_GRAPHS, HID>>>(b3, C, rb, out);
}

// round 8
// speedup vs baseline: 2.0875x; 1.3880x over previous
#include <cuda_runtime.h>

#define MAX_NODES 100000
#define MAX_EDGES 1600000
#define N_GRAPHS  1024
#define N_FEAT    128
#define HID       64
#define N_CLASSES 16
#define N_CENT    3

#define SCAN_ELEMS 1024                 // elements per scan block
#define MAX_SCAN_BLOCKS 128             // ceil(100000/1024)=98

// ---------------- scratch (no allocation allowed) ----------------
__device__ int   g_indeg   [MAX_NODES];
__device__ int   g_rowstart[MAX_NODES];
__device__ int   g_cursor  [MAX_NODES];
__device__ int   g_csr_src [MAX_EDGES];
__device__ int   g_bsum    [MAX_SCAN_BLOCKS];
__device__ int   g_boff    [MAX_SCAN_BLOCKS];
__device__ float g_dinv[MAX_NODES];
__device__ float g_hw  [(size_t)MAX_NODES * HID];
__device__ float g_agg [(size_t)MAX_NODES * HID];
__device__ float g_sums[N_GRAPHS * HID];
__device__ float g_cnt [N_GRAPHS];

// ---------------- degree ----------------
__global__ void k_zero_indeg(int n) {
    int i = blockIdx.x * blockDim.x + threadIdx.x;
    if (i < n) g_indeg[i] = 0;
}

__global__ void k_count(const int* __restrict__ dst, int E) {
    int e = blockIdx.x * blockDim.x + threadIdx.x;
    if (e < E) atomicAdd(&g_indeg[dst[e]], 1);
}

// ---------------- 3-phase exclusive scan of indeg ----------------
// Phase 1: per-block local exclusive prefix + block sum; fuses dinv.
__global__ void __launch_bounds__(256) k_scan1(int n) {
    __shared__ int warp_sums[8];
    const int t    = threadIdx.x;
    const int base = blockIdx.x * SCAN_ELEMS + t * 4;

    int v0 = 0, v1 = 0, v2 = 0, v3 = 0;
    if (base + 3 < n) {
        v0 = g_indeg[base];     v1 = g_indeg[base + 1];
        v2 = g_indeg[base + 2]; v3 = g_indeg[base + 3];
    } else {
        if (base     < n) v0 = g_indeg[base];
        if (base + 1 < n) v1 = g_indeg[base + 1];
        if (base + 2 < n) v2 = g_indeg[base + 2];
        if (base + 3 < n) v3 = g_indeg[base + 3];
    }
    int tsum = v0 + v1 + v2 + v3;

    const int lane = t & 31, wid = t >> 5;
    int inc = tsum;
#pragma unroll
    for (int off = 1; off < 32; off <<= 1) {
        int x = __shfl_up_sync(0xffffffffu, inc, off);
        if (lane >= off) inc += x;
    }
    if (lane == 31) warp_sums[wid] = inc;
    __syncthreads();
    if (t < 8) {
        int s = warp_sums[t];
#pragma unroll
        for (int off = 1; off < 8; off <<= 1) {
            int x = __shfl_up_sync(0xffu, s, off);
            if (t >= off) s += x;
        }
        warp_sums[t] = s;           // inclusive over warps
    }
    __syncthreads();

    int excl = inc - tsum + (wid > 0 ? warp_sums[wid - 1] : 0);
    int run = excl;
    if (base     < n) { g_rowstart[base]     = run; run += v0; }
    if (base + 1 < n) { g_rowstart[base + 1] = run; run += v1; }
    if (base + 2 < n) { g_rowstart[base + 2] = run; run += v2; }
    if (base + 3 < n) { g_rowstart[base + 3] = run; run += v3; }
    if (t == 255) g_bsum[blockIdx.x] = warp_sums[7];

    // fused dinv (deg includes +1 self-loop)
    if (base     < n) g_dinv[base]     = rsqrtf((float)(v0 + 1));
    if (base + 1 < n) g_dinv[base + 1] = rsqrtf((float)(v1 + 1));
    if (base + 2 < n) g_dinv[base + 2] = rsqrtf((float)(v2 + 1));
    if (base + 3 < n) g_dinv[base + 3] = rsqrtf((float)(v3 + 1));
}

// Phase 2: scan the <=128 block sums (one block of 128 threads).
__global__ void k_scan2(int nb) {
    __shared__ int ws[4];
    const int t = threadIdx.x;               // 128 threads
    int v = (t < nb) ? g_bsum[t] : 0;
    const int lane = t & 31, wid = t >> 5;
    int inc = v;
#pragma unroll
    for (int off = 1; off < 32; off <<= 1) {
        int x = __shfl_up_sync(0xffffffffu, inc, off);
        if (lane >= off) inc += x;
    }
    if (lane == 31) ws[wid] = inc;
    __syncthreads();
    if (t < 4) {
        int s = ws[t];
#pragma unroll
        for (int off = 1; off < 4; off <<= 1) {
            int x = __shfl_up_sync(0xfu, s, off);
            if (t >= off) s += x;
        }
        ws[t] = s;
    }
    __syncthreads();
    int excl = inc - v + (wid > 0 ? ws[wid - 1] : 0);
    if (t < nb) g_boff[t] = excl;
}

// Phase 3: apply block offsets, init cursor.
__global__ void k_scan3(int n) {
    int i = blockIdx.x * blockDim.x + threadIdx.x;
    if (i < n) {
        int r = g_rowstart[i] + g_boff[i >> 10];
        g_rowstart[i] = r;
        g_cursor[i]   = r;
    }
}

__global__ void k_fill(const int* __restrict__ src, const int* __restrict__ dst, int E) {
    int e = blockIdx.x * blockDim.x + threadIdx.x;
    if (e < E) {
        int pos = atomicAdd(&g_cursor[dst[e]], 1);
        g_csr_src[pos] = src[e];
    }
}

// ---------------- GEMM: g_hw[n,64] = act(in[n,K]) @ W[K,64] ----------------
template <int K, bool FROM_AGG, bool ACT>
__global__ void __launch_bounds__(256) k_gemm(const float* __restrict__ in,
                                              const float* __restrict__ W,
                                              const float* __restrict__ bias, int n) {
    constexpr int XS_STRIDE = K + 4;
    __shared__ float Ws[K * HID];
    __shared__ float Xs[64 * XS_STRIDE];
    __shared__ float Bs[K];

    const int tid  = threadIdx.x;
    const int base = blockIdx.x * 64;

    for (int i = tid; i < K * HID; i += 256) Ws[i] = W[i];
    if (ACT) for (int i = tid; i < K; i += 256) Bs[i] = bias[i];

    const float* xin = FROM_AGG ? (const float*)g_agg : in;
    for (int i = tid; i < 64 * (K / 4); i += 256) {
        int r = i / (K / 4), kq = i - r * (K / 4);
        int node = base + r;
        float4 v = make_float4(0.f, 0.f, 0.f, 0.f);
        if (node < n) v = ((const float4*)(xin + (size_t)node * K))[kq];
        float* xr = Xs + r * XS_STRIDE + kq * 4;
        xr[0] = v.x; xr[1] = v.y; xr[2] = v.z; xr[3] = v.w;
    }
    __syncthreads();

    const int cg = tid & 15;
    const int ng = tid >> 4;
    float acc[4][4];
#pragma unroll
    for (int i = 0; i < 4; i++)
#pragma unroll
        for (int j = 0; j < 4; j++) acc[i][j] = 0.0f;

#pragma unroll 4
    for (int k = 0; k < K; k++) {
        float4 w = *(const float4*)(Ws + k * HID + cg * 4);
        float xv[4];
#pragma unroll
        for (int i = 0; i < 4; i++) {
            float v = Xs[(ng + 16 * i) * XS_STRIDE + k];
            if (ACT) v = fmaxf(v + Bs[k], 0.0f);
            xv[i] = v;
        }
#pragma unroll
        for (int i = 0; i < 4; i++) {
            acc[i][0] = fmaf(xv[i], w.x, acc[i][0]);
            acc[i][1] = fmaf(xv[i], w.y, acc[i][1]);
            acc[i][2] = fmaf(xv[i], w.z, acc[i][2]);
            acc[i][3] = fmaf(xv[i], w.w, acc[i][3]);
        }
    }

#pragma unroll
    for (int i = 0; i < 4; i++) {
        int node = base + ng + 16 * i;
        if (node < n) {
            float4 v = make_float4(acc[i][0], acc[i][1], acc[i][2], acc[i][3]);
            *((float4*)(g_hw + (size_t)node * HID + cg * 4)) = v;
        }
    }
}

// ---------------- gather: agg[d,:] = dinv[d]^2*hw[d,:] + sum_e dinv[s]dinv[d]*hw[s,:] ----------------
__global__ void k_gather(int n) {
    int w    = (blockIdx.x * blockDim.x + threadIdx.x) >> 5;
    int lane = threadIdx.x & 31;
    if (w >= n) return;
    float dd = g_dinv[w];
    const float* hw0 = g_hw + (size_t)w * HID;
    float a0 = dd * dd * hw0[lane];
    float a1 = dd * dd * hw0[lane + 32];
    int beg = g_rowstart[w];
    int end = beg + g_indeg[w];
    int j = beg;
    if (j < end) {
        int s = g_csr_src[j];
        for (; j + 1 < end; j++) {
            int s_next = g_csr_src[j + 1];
            float nrm = dd * g_dinv[s];
            const float* hs = g_hw + (size_t)s * HID;
            a0 = fmaf(nrm, hs[lane],      a0);
            a1 = fmaf(nrm, hs[lane + 32], a1);
            s = s_next;
        }
        float nrm = dd * g_dinv[s];
        const float* hs = g_hw + (size_t)s * HID;
        a0 = fmaf(nrm, hs[lane],      a0);
        a1 = fmaf(nrm, hs[lane + 32], a1);
    }
    g_agg[(size_t)w * HID + lane]      = a0;
    g_agg[(size_t)w * HID + lane + 32] = a1;
}

// ---------------- pooling ----------------
__global__ void k_zero_pool() {
    int idx = blockIdx.x * blockDim.x + threadIdx.x;
    if (idx < N_GRAPHS * HID) g_sums[idx] = 0.0f;
    if (idx < N_GRAPHS)       g_cnt[idx]  = 0.0f;
}

__global__ void k_pool(const int* __restrict__ batch, int n) {
    int w    = (blockIdx.x * blockDim.x + threadIdx.x) >> 5;
    int lane = threadIdx.x & 31;
    if (w >= n) return;
    int b = batch[w];
    atomicAdd(&g_sums[b * HID + lane],      g_agg[(size_t)w * HID + lane]);
    atomicAdd(&g_sums[b * HID + lane + 32], g_agg[(size_t)w * HID + lane + 32]);
    if (lane == 0) atomicAdd(&g_cnt[b], 1.0f);
}

// ---------------- head ----------------
__global__ void k_head(const float* __restrict__ b3, const float* __restrict__ C,
                       const float* __restrict__ rbias, float* __restrict__ out) {
    int g = blockIdx.x;
    int tid = threadIdx.x;   // 64 threads
    __shared__ float emb[HID];
    __shared__ float d48[N_CLASSES * N_CENT];
    __shared__ float dpc[N_CLASSES];

    float cnt = fmaxf(g_cnt[g], 1.0f);
    emb[tid] = g_sums[g * HID + tid] / cnt + b3[tid];
    __syncthreads();

    if (tid < N_CLASSES * N_CENT) {
        const float* c = C + tid * HID;
        float acc = 0.0f;
#pragma unroll
        for (int k = 0; k < HID; k++) {
            float df = emb[k] - c[k];
            acc = fmaf(df, df, acc);
        }
        d48[tid] = acc;
    }
    __syncthreads();
    if (tid < N_CLASSES) {
        float m = fminf(d48[tid * 3], fminf(d48[tid * 3 + 1], d48[tid * 3 + 2]));
        dpc[tid] = m;
        out[g * 17 + tid] = -m;
    }
    __syncthreads();
    if (tid == 0) {
        float m = dpc[0];
#pragma unroll
        for (int i = 1; i < N_CLASSES; i++) m = fminf(m, dpc[i]);
        out[g * 17 + 16] = m - rbias[0];
    }
}

// ---------------- launch ----------------
extern "C" void kernel_launch(void* const* d_in, const int* in_sizes, int n_in,
                              void* d_out, int out_size) {
    const float* x     = (const float*)d_in[0];
    const int*   ei    = (const int*)d_in[1];     // JAX default int32
    const int*   batch = (const int*)d_in[2];
    const float* W1    = (const float*)d_in[3];
    const float* b1    = (const float*)d_in[4];
    const float* W2    = (const float*)d_in[5];
    const float* b2    = (const float*)d_in[6];
    const float* W3    = (const float*)d_in[7];
    const float* b3    = (const float*)d_in[8];
    const float* C     = (const float*)d_in[9];
    const float* rb    = (const float*)d_in[10];
    float* out = (float*)d_out;

    int n = in_sizes[0] / N_FEAT;
    int E = in_sizes[1] / 2;
    const int* src = ei;
    const int* dst = ei + E;

    int scanBlocks = (n + SCAN_ELEMS - 1) / SCAN_ELEMS;

    // ---- CSR build ----
    k_zero_indeg<<<(n + 255) / 256, 256>>>(n);
    k_count<<<(E + 255) / 256, 256>>>(dst, E);
    k_scan1<<<scanBlocks, 256>>>(n);
    k_scan2<<<1, 128>>>(scanBlocks);
    k_scan3<<<(n + 255) / 256, 256>>>(n);
    k_fill<<<(E + 255) / 256, 256>>>(src, dst, E);

    int gemmBlocks   = (n + 63) / 64;
    int gatherBlocks = (int)(((long long)n * 32 + 255) / 256);

    // ---- layer 1 ----
    k_gemm<N_FEAT, false, false><<<gemmBlocks, 256>>>(x, W1, nullptr, n);
    k_gather<<<gatherBlocks, 256>>>(n);

    // ---- layer 2 (bias1+relu folded) ----
    k_gemm<HID, true, true><<<gemmBlocks, 256>>>(nullptr, W2, b1, n);
    k_gather<<<gatherBlocks, 256>>>(n);

    // ---- layer 3 (bias2+relu folded) ----
    k_gemm<HID, true, true><<<gemmBlocks, 256>>>(nullptr, W3, b2, n);
    k_gather<<<gatherBlocks, 256>>>(n);

    // ---- pool (bias3 folded into head) ----
    k_zero_pool<<<(N_GRAPHS * HID + 255) / 256, 256>>>();
    k_pool<<<gatherBlocks, 256>>>(batch, n);

    // ---- head ----
    k_head<<<N_GRAPHS, HID>>>(b3, C, rb, out);
}